// round 1
// baseline (speedup 1.0000x reference)
#include <cuda_runtime.h>
#include <math.h>

#define B_ 64
#define T_ 512
#define D_ 1024
#define H_ 1024
#define G_ 4096

// Scratch (allocation-free rule: __device__ globals)
__device__ float g_xg[(size_t)B_ * T_ * G_];   // [T][B][4H] pre-activations incl. bias
__device__ float g_h[2][B_ * H_];              // ping-pong hidden state
__device__ float g_c[B_ * H_];                 // cell state

__global__ void init_kernel() {
    int i = blockIdx.x * blockDim.x + threadIdx.x;
    if (i < B_ * H_) {
        g_h[0][i] = 0.f;
        g_h[1][i] = 0.f;
        g_c[i]    = 0.f;
    }
}

// Phase A: x_gates[t][b][n] = sum_k feature[b][t][k] * W_ih[n][k] + b_ih[n] + b_hh[n]
// Tile: 64 (b) x 64 (n), K-tile 16. Block covers a single t (all 64 batches).
__global__ __launch_bounds__(256) void gemm_xg_kernel(
    const float* __restrict__ feature, const float* __restrict__ W_ih,
    const float* __restrict__ b_ih, const float* __restrict__ b_hh)
{
    __shared__ __align__(16) float As[16][68];  // [k][m]
    __shared__ __align__(16) float Bs[16][68];  // [k][n]
    int tid = threadIdx.x;
    int tx = tid & 15, ty = tid >> 4;           // n-quad, m-quad
    int n0 = blockIdx.x * 64;
    int t  = blockIdx.y;
    int lr = tid >> 2;                          // staging row 0..63
    int lk = (tid & 3) * 4;                     // staging k offset 0,4,8,12

    const float* fptr = feature + ((size_t)lr * T_ + t) * D_ + lk;   // b = lr
    const float* wptr = W_ih + (size_t)(n0 + lr) * D_ + lk;

    float acc[4][4] = {};

    for (int k0 = 0; k0 < D_; k0 += 16) {
        float4 av = *(const float4*)(fptr + k0);
        float4 bv = *(const float4*)(wptr + k0);
        __syncthreads();
        As[lk + 0][lr] = av.x; As[lk + 1][lr] = av.y;
        As[lk + 2][lr] = av.z; As[lk + 3][lr] = av.w;
        Bs[lk + 0][lr] = bv.x; Bs[lk + 1][lr] = bv.y;
        Bs[lk + 2][lr] = bv.z; Bs[lk + 3][lr] = bv.w;
        __syncthreads();
#pragma unroll
        for (int k = 0; k < 16; k++) {
            float4 a4 = *(const float4*)&As[k][ty * 4];
            float4 b4 = *(const float4*)&Bs[k][tx * 4];
            acc[0][0] = fmaf(a4.x, b4.x, acc[0][0]);
            acc[0][1] = fmaf(a4.x, b4.y, acc[0][1]);
            acc[0][2] = fmaf(a4.x, b4.z, acc[0][2]);
            acc[0][3] = fmaf(a4.x, b4.w, acc[0][3]);
            acc[1][0] = fmaf(a4.y, b4.x, acc[1][0]);
            acc[1][1] = fmaf(a4.y, b4.y, acc[1][1]);
            acc[1][2] = fmaf(a4.y, b4.z, acc[1][2]);
            acc[1][3] = fmaf(a4.y, b4.w, acc[1][3]);
            acc[2][0] = fmaf(a4.z, b4.x, acc[2][0]);
            acc[2][1] = fmaf(a4.z, b4.y, acc[2][1]);
            acc[2][2] = fmaf(a4.z, b4.z, acc[2][2]);
            acc[2][3] = fmaf(a4.z, b4.w, acc[2][3]);
            acc[3][0] = fmaf(a4.w, b4.x, acc[3][0]);
            acc[3][1] = fmaf(a4.w, b4.y, acc[3][1]);
            acc[3][2] = fmaf(a4.w, b4.z, acc[3][2]);
            acc[3][3] = fmaf(a4.w, b4.w, acc[3][3]);
        }
    }

    int n = n0 + tx * 4;
    float bx = b_ih[n + 0] + b_hh[n + 0];
    float by_ = b_ih[n + 1] + b_hh[n + 1];
    float bz = b_ih[n + 2] + b_hh[n + 2];
    float bw = b_ih[n + 3] + b_hh[n + 3];
#pragma unroll
    for (int i = 0; i < 4; i++) {
        int b = ty * 4 + i;
        float4 v = make_float4(acc[i][0] + bx, acc[i][1] + by_,
                               acc[i][2] + bz, acc[i][3] + bw);
        *(float4*)(g_xg + ((size_t)t * B_ + b) * G_ + n) = v;
    }
}

__device__ __forceinline__ float sigf(float x) {
    return 1.f / (1.f + __expf(-x));
}

// Phase B: one step. Block bx owns hidden units [8*bx, 8*bx+8) x 4 gates x 64 batches.
// Local column c_local = gate*8 + u  -> global gate row g = gate*H + j0 + u.
__global__ __launch_bounds__(256) void lstm_step_kernel(
    const float* __restrict__ W_hh, const int* __restrict__ seq_len,
    float* __restrict__ out, int t)
{
    __shared__ __align__(16) float hs[64][68];   // [b][k]
    __shared__ __align__(16) float ws[32][68];   // [c_local][k]
    __shared__ float gsm[64][33];                // gate pre-activations

    const float* __restrict__ h_in  = g_h[t & 1];
    float* __restrict__ h_out       = g_h[(t + 1) & 1];
    const float* __restrict__ xg_t  = g_xg + (size_t)t * B_ * G_;

    int tid = threadIdx.x;
    int j0 = blockIdx.x * 8;
    int cx = tid & 15, by = tid >> 4;            // cols {2cx,2cx+1}, batches 4by..4by+3

    // staging indices
    int hr = tid >> 2;  int hk = (tid & 3) * 16; // hs: 4 threads/row, 16 floats each
    int wr = tid >> 3;  int wk = (tid & 7) * 8;  // ws: 8 threads/row, 8 floats each
    int wgate = wr >> 3, wu = wr & 7;
    const float* hptr = h_in + hr * H_ + hk;
    const float* wptr = W_hh + (size_t)(wgate * H_ + j0 + wu) * H_ + wk;

    float acc[4][2] = {};

    for (int k0 = 0; k0 < H_; k0 += 64) {
        float4 h0 = *(const float4*)(hptr + k0 + 0);
        float4 h1 = *(const float4*)(hptr + k0 + 4);
        float4 h2 = *(const float4*)(hptr + k0 + 8);
        float4 h3 = *(const float4*)(hptr + k0 + 12);
        float4 w0 = *(const float4*)(wptr + k0 + 0);
        float4 w1 = *(const float4*)(wptr + k0 + 4);
        __syncthreads();
        *(float4*)&hs[hr][hk + 0]  = h0;
        *(float4*)&hs[hr][hk + 4]  = h1;
        *(float4*)&hs[hr][hk + 8]  = h2;
        *(float4*)&hs[hr][hk + 12] = h3;
        *(float4*)&ws[wr][wk + 0]  = w0;
        *(float4*)&ws[wr][wk + 4]  = w1;
        __syncthreads();
#pragma unroll
        for (int kk = 0; kk < 64; kk += 4) {
            float4 wa = *(const float4*)&ws[2 * cx][kk];
            float4 wb = *(const float4*)&ws[2 * cx + 1][kk];
#pragma unroll
            for (int i = 0; i < 4; i++) {
                float4 hv = *(const float4*)&hs[4 * by + i][kk];
                acc[i][0] = fmaf(hv.x, wa.x, acc[i][0]);
                acc[i][0] = fmaf(hv.y, wa.y, acc[i][0]);
                acc[i][0] = fmaf(hv.z, wa.z, acc[i][0]);
                acc[i][0] = fmaf(hv.w, wa.w, acc[i][0]);
                acc[i][1] = fmaf(hv.x, wb.x, acc[i][1]);
                acc[i][1] = fmaf(hv.y, wb.y, acc[i][1]);
                acc[i][1] = fmaf(hv.z, wb.z, acc[i][1]);
                acc[i][1] = fmaf(hv.w, wb.w, acc[i][1]);
            }
        }
    }

    // Add precomputed input gates, stash into shared for the cell update.
#pragma unroll
    for (int i = 0; i < 4; i++) {
        int b = 4 * by + i;
#pragma unroll
        for (int j = 0; j < 2; j++) {
            int cl = 2 * cx + j;
            int g = (cl >> 3) * H_ + j0 + (cl & 7);
            gsm[b][cl] = acc[i][j] + xg_t[b * G_ + g];
        }
    }
    __syncthreads();

    // Pointwise LSTM cell: 64 batches x 8 units = 512 items.
    for (int it = tid; it < 512; it += 256) {
        int b = it >> 3, u = it & 7;
        int j = j0 + u;
        float xi = gsm[b][u];
        float xf = gsm[b][8 + u];
        float xg = gsm[b][16 + u];
        float xo = gsm[b][24 + u];
        float si = sigf(xi);
        float sf = sigf(xf);
        float tg = tanhf(xg);
        float so = sigf(xo);
        float cold = g_c[b * H_ + j];
        float cnew = fmaf(sf, cold, si * tg);
        float hnew = so * tanhf(cnew);
        float hold = h_in[b * H_ + j];
        bool m = t < seq_len[b];
        h_out[b * H_ + j] = m ? hnew : hold;
        g_c[b * H_ + j]   = m ? cnew : cold;
        out[((size_t)b * T_ + t) * H_ + j] = m ? hnew : 0.f;
    }
}

extern "C" void kernel_launch(void* const* d_in, const int* in_sizes, int n_in,
                              void* d_out, int out_size)
{
    const float* feature = (const float*)d_in[0];
    const float* W_ih    = (const float*)d_in[1];
    const float* W_hh    = (const float*)d_in[2];
    const float* b_ih    = (const float*)d_in[3];
    const float* b_hh    = (const float*)d_in[4];
    const int*   seq_len = (const int*)d_in[5];
    float* out = (float*)d_out;

    init_kernel<<<(B_ * H_ + 255) / 256, 256>>>();
    gemm_xg_kernel<<<dim3(G_ / 64, T_), 256>>>(feature, W_ih, b_ih, b_hh);
    for (int t = 0; t < T_; t++) {
        lstm_step_kernel<<<128, 256>>>(W_hh, seq_len, out, t);
    }
}

// round 4
// speedup vs baseline: 1.7452x; 1.7452x over previous
#include <cuda_runtime.h>
#include <cuda_bf16.h>
#include <math.h>
#include <stdint.h>

#define B_ 64
#define T_ 512
#define D_ 1024
#define H_ 1024
#define G_ 4096

// ---------------- device scratch (allocation-free rule) ----------------
__device__ float g_xg[(size_t)T_ * B_ * G_];            // [T][B][4H] pre-activations
__device__ float g_h[2][B_ * H_];                       // fp32 hidden (ping-pong)
__device__ float g_c[B_ * H_];                          // cell state
__device__ __nv_bfloat16 g_hh[128 * H_];                // rows 0-63: h_hi, 64-127: h_lo
__device__ __nv_bfloat16 g_WW[(size_t)G_ * 2 * H_];     // [4096][2048]: 0-1023 W_hi, 1024-2047 W_lo

#define SWZ(off) ((off) ^ (((off) >> 3) & 0x70))

__device__ __forceinline__ uint32_t smem_to_u32(const void* p) {
    uint32_t a;
    asm("{ .reg .u64 t; cvta.to.shared.u64 t, %1; cvt.u32.u64 %0, t; }" : "=r"(a) : "l"(p));
    return a;
}

__device__ __forceinline__ void ldsm_x4(uint32_t& r0, uint32_t& r1, uint32_t& r2,
                                        uint32_t& r3, uint32_t addr) {
    asm volatile("ldmatrix.sync.aligned.m8n8.x4.shared.b16 {%0,%1,%2,%3}, [%4];"
                 : "=r"(r0), "=r"(r1), "=r"(r2), "=r"(r3) : "r"(addr));
}

__device__ __forceinline__ void hmma16816(float* d, uint32_t a0, uint32_t a1,
                                          uint32_t a2, uint32_t a3,
                                          uint32_t b0, uint32_t b1) {
    asm volatile(
        "mma.sync.aligned.m16n8k16.row.col.f32.bf16.bf16.f32 "
        "{%0,%1,%2,%3}, {%4,%5,%6,%7}, {%8,%9}, {%0,%1,%2,%3};"
        : "+f"(d[0]), "+f"(d[1]), "+f"(d[2]), "+f"(d[3])
        : "r"(a0), "r"(a1), "r"(a2), "r"(a3), "r"(b0), "r"(b1));
}

// ---------------- init kernels ----------------
__global__ void init_state_kernel() {
    int i = blockIdx.x * blockDim.x + threadIdx.x;
    if (i < B_ * H_) {
        g_h[0][i] = 0.f; g_h[1][i] = 0.f; g_c[i] = 0.f;
    }
    if (i < 128 * H_) {
        g_hh[i] = __float2bfloat16(0.f);
    }
}

__global__ void build_WW_kernel(const float* __restrict__ W_hh) {
    int i = blockIdx.x * blockDim.x + threadIdx.x;
    if (i < G_ * H_) {
        int row = i >> 10, col = i & 1023;
        float w = W_hh[i];
        __nv_bfloat16 hi = __float2bfloat16(w);
        __nv_bfloat16 lo = __float2bfloat16(w - __bfloat162float(hi));
        g_WW[(size_t)row * 2048 + col] = hi;
        g_WW[(size_t)row * 2048 + 1024 + col] = lo;
    }
}

// ---------------- Phase A: x_gates GEMM (fp32, proven R1) ----------------
__global__ __launch_bounds__(256) void gemm_xg_kernel(
    const float* __restrict__ feature, const float* __restrict__ W_ih,
    const float* __restrict__ b_ih, const float* __restrict__ b_hh)
{
    __shared__ __align__(16) float As[16][68];
    __shared__ __align__(16) float Bs[16][68];
    int tid = threadIdx.x;
    int tx = tid & 15, ty = tid >> 4;
    int n0 = blockIdx.x * 64;
    int t  = blockIdx.y;
    int lr = tid >> 2;
    int lk = (tid & 3) * 4;

    const float* fptr = feature + ((size_t)lr * T_ + t) * D_ + lk;
    const float* wptr = W_ih + (size_t)(n0 + lr) * D_ + lk;

    float acc[4][4] = {};
    for (int k0 = 0; k0 < D_; k0 += 16) {
        float4 av = *(const float4*)(fptr + k0);
        float4 bv = *(const float4*)(wptr + k0);
        __syncthreads();
        As[lk + 0][lr] = av.x; As[lk + 1][lr] = av.y;
        As[lk + 2][lr] = av.z; As[lk + 3][lr] = av.w;
        Bs[lk + 0][lr] = bv.x; Bs[lk + 1][lr] = bv.y;
        Bs[lk + 2][lr] = bv.z; Bs[lk + 3][lr] = bv.w;
        __syncthreads();
#pragma unroll
        for (int k = 0; k < 16; k++) {
            float4 a4 = *(const float4*)&As[k][ty * 4];
            float4 b4 = *(const float4*)&Bs[k][tx * 4];
            acc[0][0] = fmaf(a4.x, b4.x, acc[0][0]);
            acc[0][1] = fmaf(a4.x, b4.y, acc[0][1]);
            acc[0][2] = fmaf(a4.x, b4.z, acc[0][2]);
            acc[0][3] = fmaf(a4.x, b4.w, acc[0][3]);
            acc[1][0] = fmaf(a4.y, b4.x, acc[1][0]);
            acc[1][1] = fmaf(a4.y, b4.y, acc[1][1]);
            acc[1][2] = fmaf(a4.y, b4.z, acc[1][2]);
            acc[1][3] = fmaf(a4.y, b4.w, acc[1][3]);
            acc[2][0] = fmaf(a4.z, b4.x, acc[2][0]);
            acc[2][1] = fmaf(a4.z, b4.y, acc[2][1]);
            acc[2][2] = fmaf(a4.z, b4.z, acc[2][2]);
            acc[2][3] = fmaf(a4.z, b4.w, acc[2][3]);
            acc[3][0] = fmaf(a4.w, b4.x, acc[3][0]);
            acc[3][1] = fmaf(a4.w, b4.y, acc[3][1]);
            acc[3][2] = fmaf(a4.w, b4.z, acc[3][2]);
            acc[3][3] = fmaf(a4.w, b4.w, acc[3][3]);
        }
    }
    int n = n0 + tx * 4;
    float bx = b_ih[n + 0] + b_hh[n + 0];
    float by_ = b_ih[n + 1] + b_hh[n + 1];
    float bz = b_ih[n + 2] + b_hh[n + 2];
    float bw = b_ih[n + 3] + b_hh[n + 3];
#pragma unroll
    for (int i = 0; i < 4; i++) {
        int b = ty * 4 + i;
        float4 v = make_float4(acc[i][0] + bx, acc[i][1] + by_,
                               acc[i][2] + bz, acc[i][3] + bw);
        *(float4*)(g_xg + ((size_t)t * B_ + b) * G_ + n) = v;
    }
}

__device__ __forceinline__ float sigf(float x) { return 1.f / (1.f + __expf(-x)); }

// ---------------- Phase B: one recurrent step via mma.sync (HMMA bf16) --------
// D[128][32] = [h_hi;h_lo] @ (W_hi|W_lo rows)^T, accumulated over 2 passes.
// Block bx owns 8 hidden units j0=8*bx; gate-column n = gate*8+u.
// 8 warps; warp w owns D rows [16w,16w+16). K staged in 8 chunks of 128.
// SMEM: A [2 subtiles][128 rows x 128B], B [pass][subtile][32 rows x 128B].
static constexpr int SM_A = 0;          // 2 x 16384
static constexpr int SM_B = 32768;      // 4 x 4096
static constexpr int SM_BYTES = 49152;  // exactly 48KB static

__global__ __launch_bounds__(256, 1) void lstm_step_mma(
    const int* __restrict__ seq_len, float* __restrict__ out, int t)
{
    __shared__ __align__(1024) uint8_t smem[SM_BYTES];
    uint32_t sbase = smem_to_u32(smem);

    int tid = threadIdx.x;
    int wid = tid >> 5, lane = tid & 31;
    int g = lane >> 2, tg = lane & 3;
    int j0 = blockIdx.x * 8;
    int m0 = wid * 16;

    // staging indices (loop-invariant)
    int srow = tid >> 4;            // 0..15
    int e8   = (tid & 15) * 8;      // element col 0..120
    int ec   = e8 >> 6;             // subtile 0/1
    uint32_t ekw = (uint32_t)((e8 & 63) * 2);  // byte col within subtile row

    // ldmatrix lane addressing
    int q = lane >> 3, r8 = lane & 7;
    uint32_t a_row = (uint32_t)(m0 + r8 + (q & 1) * 8);
    uint32_t a_kb  = (uint32_t)((q >> 1) * 16);
    uint32_t b_rowq = (uint32_t)(r8 + (q >> 1) * 8);     // + tp*16
    uint32_t b_kb  = (uint32_t)((q & 1) * 16);

    float acc[4][4] = {};

    for (int st = 0; st < 8; st++) {
        int kc = st * 128;

        // global loads first (no smem dependency)
        uint4 va[8];
#pragma unroll
        for (int i = 0; i < 8; i++) {
            int row = srow + i * 16;
            va[i] = *(const uint4*)(g_hh + (size_t)row * H_ + kc + e8);
        }
        uint4 vb[4];
#pragma unroll
        for (int i = 0; i < 4; i++) {
            int p = i >> 1;
            int lr = srow + (i & 1) * 16;
            int gn = (lr >> 3) * H_ + j0 + (lr & 7);
            vb[i] = *(const uint4*)(g_WW + (size_t)gn * 2048 + p * 1024 + kc + e8);
        }

        __syncthreads();   // previous chunk fully consumed

#pragma unroll
        for (int i = 0; i < 8; i++) {
            int row = srow + i * 16;
            *(uint4*)(smem + SM_A + ec * 16384 + SWZ((uint32_t)(row * 128) + ekw)) = va[i];
        }
#pragma unroll
        for (int i = 0; i < 4; i++) {
            int p = i >> 1;
            int lr = srow + (i & 1) * 16;
            *(uint4*)(smem + SM_B + (p * 2 + ec) * 4096 + SWZ((uint32_t)(lr * 128) + ekw)) = vb[i];
        }
        __syncthreads();

        // compute: 2 subtiles x 4 k16-iters
#pragma unroll
        for (int c = 0; c < 2; c++) {
#pragma unroll
            for (int kk = 0; kk < 4; kk++) {
                uint32_t a0, a1, a2, a3;
                ldsm_x4(a0, a1, a2, a3,
                        sbase + SM_A + c * 16384 +
                        SWZ(a_row * 128 + (uint32_t)(kk * 32) + a_kb));
#pragma unroll
                for (int p = 0; p < 2; p++) {
#pragma unroll
                    for (int tp = 0; tp < 2; tp++) {
                        uint32_t b0, b1, b2, b3;
                        ldsm_x4(b0, b1, b2, b3,
                                sbase + SM_B + (p * 2 + c) * 4096 +
                                SWZ((b_rowq + tp * 16) * 128 + (uint32_t)(kk * 32) + b_kb));
                        hmma16816(acc[tp * 2 + 0], a0, a1, a2, a3, b0, b1);
                        hmma16816(acc[tp * 2 + 1], a0, a1, a2, a3, b2, b3);
                    }
                }
            }
        }
    }
    __syncthreads();   // all MMA done; smem free for reuse

    // ---- epilogue: gates[b][n] = D[b][n] + D[b+64][n] ----
    float* ssum = (float*)smem;   // [64][33]
    if (wid >= 4) {
        int b0r = (wid - 4) * 16 + g;
#pragma unroll
        for (int nt = 0; nt < 4; nt++) {
            int n = nt * 8 + tg * 2;
            ssum[b0r * 33 + n]           = acc[nt][0];
            ssum[b0r * 33 + n + 1]       = acc[nt][1];
            ssum[(b0r + 8) * 33 + n]     = acc[nt][2];
            ssum[(b0r + 8) * 33 + n + 1] = acc[nt][3];
        }
    }
    __syncthreads();

    if (wid < 4) {
        const float* __restrict__ h_in = g_h[t & 1];
        float* __restrict__ h_out = g_h[(t + 1) & 1];
#pragma unroll
        for (int rs = 0; rs < 2; rs++) {
            int b = wid * 16 + g + rs * 8;
            const float* xgb = g_xg + ((size_t)t * B_ + b) * G_;
            bool m = t < seq_len[b];
#pragma unroll
            for (int cs = 0; cs < 2; cs++) {
                int u = tg * 2 + cs;
                int j = j0 + u;
                float xi = acc[0][rs * 2 + cs] + ssum[b * 33 + 0 * 8 + u] + xgb[j];
                float xf = acc[1][rs * 2 + cs] + ssum[b * 33 + 1 * 8 + u] + xgb[H_ + j];
                float xg = acc[2][rs * 2 + cs] + ssum[b * 33 + 2 * 8 + u] + xgb[2 * H_ + j];
                float xo = acc[3][rs * 2 + cs] + ssum[b * 33 + 3 * 8 + u] + xgb[3 * H_ + j];
                float si = sigf(xi), sf = sigf(xf), tgh = tanhf(xg), so = sigf(xo);
                float cold = g_c[b * H_ + j];
                float cn = fmaf(sf, cold, si * tgh);
                float hn = so * tanhf(cn);
                float hold = h_in[b * H_ + j];
                float he = m ? hn : hold;
                g_c[b * H_ + j] = m ? cn : cold;
                h_out[b * H_ + j] = he;
                __nv_bfloat16 hi = __float2bfloat16(he);
                g_hh[b * H_ + j] = hi;
                g_hh[(size_t)(b + 64) * H_ + j] = __float2bfloat16(he - __bfloat162float(hi));
                out[((size_t)b * T_ + t) * H_ + j] = m ? hn : 0.f;
            }
        }
    }
}

extern "C" void kernel_launch(void* const* d_in, const int* in_sizes, int n_in,
                              void* d_out, int out_size)
{
    const float* feature = (const float*)d_in[0];
    const float* W_ih    = (const float*)d_in[1];
    const float* W_hh    = (const float*)d_in[2];
    const float* b_ih    = (const float*)d_in[3];
    const float* b_hh    = (const float*)d_in[4];
    const int*   seq_len = (const int*)d_in[5];
    float* out = (float*)d_out;

    init_state_kernel<<<(128 * H_ + 255) / 256, 256>>>();
    build_WW_kernel<<<(G_ * H_ + 255) / 256, 256>>>(W_hh);
    gemm_xg_kernel<<<dim3(G_ / 64, T_), 256>>>(feature, W_ih, b_ih, b_hh);
    for (int t = 0; t < T_; t++) {
        lstm_step_mma<<<128, 256>>>(seq_len, out, t);
    }
}